// round 2
// baseline (speedup 1.0000x reference)
#include <cuda_runtime.h>
#include <cuda_bf16.h>

#define N_NODES 50000
#define DIM     128
#define N_EDGES 800000
#define BM      64

// Scratch (device globals — no allocation allowed in kernel_launch)
__device__ float g_deg [2 * N_NODES];
__device__ float g_dinv[2 * N_NODES];
__device__ float g_hs  [N_NODES * DIM];
__device__ float g_acc [N_NODES * DIM];
__device__ float g_h   [N_NODES * DIM];

// ---------------------------------------------------------------------------
// Degree: deg = 1 (self loop) + indegree; dinv = rsqrt(deg)
// ---------------------------------------------------------------------------
__global__ void k_init_deg() {
    int i = blockIdx.x * blockDim.x + threadIdx.x;
    if (i < 2 * N_NODES) g_deg[i] = 1.0f;
}

__global__ void k_count_deg(const int* __restrict__ dst, float* __restrict__ deg) {
    int e = blockIdx.x * blockDim.x + threadIdx.x;
    int stride = gridDim.x * blockDim.x;
    for (; e < N_EDGES; e += stride)
        atomicAdd(&deg[__ldg(dst + e)], 1.0f);
}

__global__ void k_dinv() {
    int i = blockIdx.x * blockDim.x + threadIdx.x;
    if (i < 2 * N_NODES) g_dinv[i] = rsqrtf(g_deg[i]);
}

// ---------------------------------------------------------------------------
// GEMM: hs[m][:] = (x[m][:] @ W) * dinv[m]; also zeroes acc rows for this tile
// Block tile 64(M) x 128(N), full K=128 split in two 64-chunks.
// smem: W chunk 64x128 (32KB) + x chunk 64x64 (16KB) = 48KB static.
// ---------------------------------------------------------------------------
__global__ __launch_bounds__(256)
void k_gemm_scale(const float* __restrict__ x, const float* __restrict__ W,
                  const float* __restrict__ dinv,
                  float* __restrict__ hs, float* __restrict__ acc) {
    __shared__ float Wsh[64 * 128];
    __shared__ float xsh[64 * 64];

    const int tid = threadIdx.x;
    const int ty = tid >> 4;     // 0..15 -> 4 rows each
    const int tx = tid & 15;     // 0..15 -> 8 cols each
    const int row0 = blockIdx.x * BM;

    float a[4][8];
#pragma unroll
    for (int i = 0; i < 4; i++)
#pragma unroll
        for (int j = 0; j < 8; j++) a[i][j] = 0.0f;

    for (int kt = 0; kt < 2; kt++) {
        // Load W[kt*64 .. +63][0..127]: 2048 float4, 8 per thread
        const float4* Wg = (const float4*)(W + kt * 64 * 128);
        float4* Ws4 = (float4*)Wsh;
#pragma unroll
        for (int r = 0; r < 8; r++)
            Ws4[tid + r * 256] = Wg[tid + r * 256];

        // Load x rows [row0, row0+64), cols [kt*64, kt*64+64): 1024 float4, 4/thread
        float4* xs4 = (float4*)xsh;
#pragma unroll
        for (int r = 0; r < 4; r++) {
            int f = tid + r * 256;
            int rr = f >> 4;          // row within tile
            int c4 = f & 15;          // float4 within 64-col chunk
            int grow = row0 + rr;
            float4 v = make_float4(0.f, 0.f, 0.f, 0.f);
            if (grow < N_NODES)
                v = ((const float4*)(x + (size_t)grow * DIM + kt * 64))[c4];
            xs4[f] = v;
        }
        __syncthreads();

#pragma unroll 8
        for (int k = 0; k < 64; k++) {
            float xv[4];
#pragma unroll
            for (int i = 0; i < 4; i++) xv[i] = xsh[(ty * 4 + i) * 64 + k];
            float4 w0 = ((const float4*)Wsh)[k * 32 + tx * 2];
            float4 w1 = ((const float4*)Wsh)[k * 32 + tx * 2 + 1];
            float wv[8] = {w0.x, w0.y, w0.z, w0.w, w1.x, w1.y, w1.z, w1.w};
#pragma unroll
            for (int i = 0; i < 4; i++)
#pragma unroll
                for (int j = 0; j < 8; j++)
                    a[i][j] = fmaf(xv[i], wv[j], a[i][j]);
        }
        __syncthreads();
    }

    // Epilogue: hs = a * dinv[row]; acc = 0
#pragma unroll
    for (int i = 0; i < 4; i++) {
        int row = row0 + ty * 4 + i;
        if (row >= N_NODES) continue;
        float d = __ldg(dinv + row);
        float4 o0 = make_float4(a[i][0] * d, a[i][1] * d, a[i][2] * d, a[i][3] * d);
        float4 o1 = make_float4(a[i][4] * d, a[i][5] * d, a[i][6] * d, a[i][7] * d);
        float4* hrow = (float4*)(hs + (size_t)row * DIM);
        float4* arow = (float4*)(acc + (size_t)row * DIM);
        hrow[tx * 2]     = o0;
        hrow[tx * 2 + 1] = o1;
        float4 z = make_float4(0.f, 0.f, 0.f, 0.f);
        arow[tx * 2]     = z;
        arow[tx * 2 + 1] = z;
    }
}

// ---------------------------------------------------------------------------
// Scatter: one warp per edge; lane l handles float4 chunk l of the 128-dim row.
// acc[dst] += hs[src]  (float4 L2 atomics, sm_90+)
// ---------------------------------------------------------------------------
__global__ __launch_bounds__(256)
void k_scatter(const int* __restrict__ src, const int* __restrict__ dst,
               const float* __restrict__ hs, float* __restrict__ acc) {
    int warp  = (blockIdx.x * blockDim.x + threadIdx.x) >> 5;
    int lane  = threadIdx.x & 31;
    int nwarp = (gridDim.x * blockDim.x) >> 5;
    const float4* hs4 = (const float4*)hs;
    float4* acc4 = (float4*)acc;
    for (int e = warp; e < N_EDGES; e += nwarp) {
        int s = __ldg(src + e);
        int d = __ldg(dst + e);
        float4 v = __ldg(hs4 + (size_t)s * 32 + lane);
        atomicAdd(acc4 + (size_t)d * 32 + lane, v);
    }
}

// ---------------------------------------------------------------------------
// Finalize: out = (acc + hs) * dinv + b, optional ReLU
// ---------------------------------------------------------------------------
__global__ __launch_bounds__(256)
void k_finalize(const float* __restrict__ acc, const float* __restrict__ hs,
                const float* __restrict__ dinv, const float* __restrict__ b,
                float* __restrict__ out, int do_relu) {
    int i = blockIdx.x * blockDim.x + threadIdx.x;   // over N_NODES*32 float4s
    if (i >= N_NODES * 32) return;
    int row = i >> 5;
    int c4  = i & 31;
    float4 a = ((const float4*)acc)[i];
    float4 h = ((const float4*)hs)[i];
    float  d = __ldg(dinv + row);
    float4 bb = ((const float4*)b)[c4];
    float4 o;
    o.x = fmaf(a.x + h.x, d, bb.x);
    o.y = fmaf(a.y + h.y, d, bb.y);
    o.z = fmaf(a.z + h.z, d, bb.z);
    o.w = fmaf(a.w + h.w, d, bb.w);
    if (do_relu) {
        o.x = fmaxf(o.x, 0.f); o.y = fmaxf(o.y, 0.f);
        o.z = fmaxf(o.z, 0.f); o.w = fmaxf(o.w, 0.f);
    }
    ((float4*)out)[i] = o;
}

// ---------------------------------------------------------------------------
// Launch
// ---------------------------------------------------------------------------
static void run_layer(const float* x, const int* esrc, const int* edst,
                      const float* W, const float* b, const float* dinv,
                      float* hs, float* acc, float* out, int do_relu) {
    k_gemm_scale<<<(N_NODES + BM - 1) / BM, 256>>>(x, W, dinv, hs, acc);
    k_scatter<<<2048, 256>>>(esrc, edst, hs, acc);
    k_finalize<<<(N_NODES * 32 + 255) / 256, 256>>>(acc, hs, dinv, b, out, do_relu);
}

extern "C" void kernel_launch(void* const* d_in, const int* in_sizes, int n_in,
                              void* d_out, int out_size) {
    const float* x1  = (const float*)d_in[0];
    const int*   ei1 = (const int*)  d_in[1];
    const float* x2  = (const float*)d_in[2];
    const int*   ei2 = (const int*)  d_in[3];
    const float* W0  = (const float*)d_in[4];
    const float* b0  = (const float*)d_in[5];
    const float* W1  = (const float*)d_in[6];
    const float* b1  = (const float*)d_in[7];
    float* out = (float*)d_out;

    const int* src1 = ei1;
    const int* dst1 = ei1 + N_EDGES;
    const int* src2 = ei2;
    const int* dst2 = ei2 + N_EDGES;

    float *deg, *dinv, *hs, *acc, *h;
    cudaGetSymbolAddress((void**)&deg,  g_deg);
    cudaGetSymbolAddress((void**)&dinv, g_dinv);
    cudaGetSymbolAddress((void**)&hs,   g_hs);
    cudaGetSymbolAddress((void**)&acc,  g_acc);
    cudaGetSymbolAddress((void**)&h,    g_h);

    // Degrees / normalization for both graphs
    k_init_deg<<<(2 * N_NODES + 255) / 256, 256>>>();
    k_count_deg<<<1024, 256>>>(dst1, deg);
    k_count_deg<<<1024, 256>>>(dst2, deg + N_NODES);
    k_dinv<<<(2 * N_NODES + 255) / 256, 256>>>();

    // Graph 1
    run_layer(x1, src1, dst1, W0, b0, dinv,            hs, acc, h,   1);
    run_layer(h,  src1, dst1, W1, b1, dinv,            hs, acc, out, 0);
    // Graph 2
    run_layer(x2, src2, dst2, W0, b0, dinv + N_NODES,  hs, acc, h,   1);
    run_layer(h,  src2, dst2, W1, b1, dinv + N_NODES,  hs, acc, out + (size_t)N_NODES * DIM, 0);
}